// round 16
// baseline (speedup 1.0000x reference)
#include <cuda_runtime.h>
#include <cuda_fp16.h>
#include <cstdint>

// ===========================================================================
// Model_55611236549533 — sm_103a.
// phaseA: fp16-acc mma, register-fused L0->L1, dynamic tiles (unchanged).
// phaseB: 1024 CTAs (one segment-pair per warp), shared weight LDS, 2x ILP,
//         restores zero-segbuf invariant + resets tile counter.
// ===========================================================================

#define F_IN   64
#define S_SEG  16384
#define TILE   64
#define BLK    256
#define GRID_A 296
#define GRID_B 1024

// strides (bytes)
#define LDW0B 144
#define LDW1B 272
#define LDXB  144
#define LDGB  144

// smem byte offsets (16B aligned)
#define O_W0   0                 // 256*144 = 36864
#define O_W1   36864             // 64*272  = 17408
#define O_X0   54272             // 64*144  =  9216
#define O_X1   63488             //            9216
#define O_G0   72704             //            9216
#define O_G1   81920             //            9216
#define O_B0   91136             // 256 f32 =  1024
#define O_B1   92160             // 64 f32  =   256
#define O_SID  92416             // 128 int =   512
#define O_TN   92928             // 2 int
#define SMEM_BYTES 92944

__device__ float g_segbuf[S_SEG * 64];        // zero at entry (invariant)
__device__ unsigned int g_tilectr = GRID_A;   // reset by phaseB each run

// ---------------------------------------------------------------- PTX utils
__device__ __forceinline__ uint32_t smem_u32(const void* p) {
    uint32_t a;
    asm("{ .reg .u64 t; cvta.to.shared.u64 t, %1; cvt.u32.u64 %0, t; }"
        : "=r"(a) : "l"(p));
    return a;
}
__device__ __forceinline__ uint32_t h2u(__half2 h) {
    return *reinterpret_cast<uint32_t*>(&h);
}
__device__ __forceinline__ uint32_t hmax2z(uint32_t u) {
    __half2 h = *reinterpret_cast<__half2*>(&u);
    __half2 r = __hmax2(h, __float2half2_rn(0.f));
    return *reinterpret_cast<uint32_t*>(&r);
}
__device__ __forceinline__ void ldmx4(uint32_t* r, uint32_t addr) {
    asm volatile("ldmatrix.sync.aligned.m8n8.x4.shared.b16 {%0,%1,%2,%3}, [%4];"
                 : "=r"(r[0]), "=r"(r[1]), "=r"(r[2]), "=r"(r[3]) : "r"(addr));
}
__device__ __forceinline__ void mma_f16a(uint32_t* d, const uint32_t* a,
                                         const uint32_t* b) {
    asm volatile(
        "mma.sync.aligned.m16n8k16.row.col.f16.f16.f16.f16 "
        "{%0,%1}, {%2,%3,%4,%5}, {%6,%7}, {%0,%1};"
        : "+r"(d[0]), "+r"(d[1])
        : "r"(a[0]), "r"(a[1]), "r"(a[2]), "r"(a[3]), "r"(b[0]), "r"(b[1]));
}

// -------------------------------------------------------------- phase A
__global__ __launch_bounds__(BLK, 2)
void phaseA_mma(const float* __restrict__ x,
                const int*   __restrict__ seg_ids,
                const float* __restrict__ tfc0_w, const float* __restrict__ tfc0_b,
                const float* __restrict__ tfc1_w, const float* __restrict__ tfc1_b,
                const float* __restrict__ rl0_w,  const float* __restrict__ rl0_b,
                const float* __restrict__ rl1_w,  const float* __restrict__ rl1_b,
                int N)
{
    extern __shared__ char smc[];
    __half* W0s = (__half*)(smc + O_W0);
    __half* W1s = (__half*)(smc + O_W1);
    float*  B0s = (float*)(smc + O_B0);
    float*  B1s = (float*)(smc + O_B1);
    int*    sid_s = (int*)(smc + O_SID);
    int*    tn_s  = (int*)(smc + O_TN);
    const uint32_t smb = smem_u32(smc);

    const int tid  = threadIdx.x;
    const int wid  = tid >> 5;
    const int lane = tid & 31;
    const int lg   = lane >> 2;
    const int lt   = lane & 3;

    for (int i = tid; i < 64 * 128; i += BLK) {
        int k = i >> 7, n = i & 127;
        W0s[n * 72 + k]         = __float2half_rn(tfc0_w[i]);
        W0s[(n + 128) * 72 + k] = __float2half_rn(rl0_w[i]);
    }
    for (int i = tid; i < 128 * 32; i += BLK) {
        int k = i >> 5, n = i & 31;
        W1s[n * 136 + k]        = __float2half_rn(tfc1_w[i]);
        W1s[(32 + n) * 136 + k] = __float2half_rn(rl1_w[i]);
    }
    if (tid < 128) { B0s[tid] = tfc0_b[tid]; B0s[128 + tid] = rl0_b[tid]; }
    if (tid < 32)  { B1s[tid] = tfc1_b[tid]; B1s[32 + tid] = rl1_b[tid]; }

    const int ntiles = (N + TILE - 1) / TILE;

    int cur = blockIdx.x;
    {
        int r = tid >> 2, q = (tid & 3) * 16;
        long g = (long)cur * TILE + r;
        bool ok = (cur < ntiles) && (g < N);
        float4 v0 = make_float4(0.f,0.f,0.f,0.f), v1 = v0, v2 = v0, v3 = v0;
        if (ok) {
            const float4* xp = reinterpret_cast<const float4*>(&x[g * F_IN + q]);
            v0 = xp[0]; v1 = xp[1]; v2 = xp[2]; v3 = xp[3];
        }
        uint32_t h0 = h2u(__floats2half2_rn(v0.x, v0.y));
        uint32_t h1 = h2u(__floats2half2_rn(v0.z, v0.w));
        uint32_t h2 = h2u(__floats2half2_rn(v1.x, v1.y));
        uint32_t h3 = h2u(__floats2half2_rn(v1.z, v1.w));
        uint32_t h4 = h2u(__floats2half2_rn(v2.x, v2.y));
        uint32_t h5 = h2u(__floats2half2_rn(v2.z, v2.w));
        uint32_t h6 = h2u(__floats2half2_rn(v3.x, v3.y));
        uint32_t h7 = h2u(__floats2half2_rn(v3.z, v3.w));
        uint32_t base = smb + O_X0 + r * LDXB + q * 2;
        asm volatile("st.shared.v4.b32 [%0], {%1,%2,%3,%4};" ::
            "r"(base), "r"(h0), "r"(h1), "r"(h2), "r"(h3));
        asm volatile("st.shared.v4.b32 [%0], {%1,%2,%3,%4};" ::
            "r"(base + 16), "r"(h4), "r"(h5), "r"(h6), "r"(h7));
        if (tid < TILE) {
            long gi = (long)cur * TILE + tid;
            sid_s[tid] = (cur < ntiles && gi < N) ? seg_ids[gi] : -1;
        }
        if (tid == 0)
            tn_s[0] = (int)atomicAdd(&g_tilectr, 1u);
    }
    __syncthreads();

    const int r0 = (wid & 3) * 16;
    const int br = wid >> 2;

    const uint32_t aX_off = (uint32_t)((r0 + (lane & 15)) * LDXB +
                                       ((lane >> 4) << 3) * 2);
    const uint32_t aX_base[2] = { smb + O_X0 + aX_off, smb + O_X1 + aX_off };
    const uint32_t b0_base = smb + O_W0 +
        (br * 128 + ((lane >> 4) << 3) + (lane & 7)) * LDW0B +
        ((lane >> 3) & 1) * 16;
    const uint32_t b1_base = smb + O_W1 +
        (br * 32 + ((lane >> 4) << 3) + (lane & 7)) * LDW1B +
        ((lane >> 3) & 1) * 16;
    const uint32_t gs_base[2] = { smb + O_G0, smb + O_G1 };

    int p = 0;
    while (cur < ntiles) {
        const int valid = min(TILE, N - cur * TILE);

        if (tid == 0)
            tn_s[p ^ 1] = (int)atomicAdd(&g_tilectr, 1u);

        uint32_t acc[16][2];
        #pragma unroll
        for (int j = 0; j < 16; ++j) {
            float2 bv = *reinterpret_cast<const float2*>(
                &B0s[br * 128 + j * 8 + 2 * lt]);
            uint32_t bp = h2u(__floats2half2_rn(bv.x, bv.y));
            acc[j][0] = bp; acc[j][1] = bp;
        }
        #pragma unroll
        for (int k2 = 0; k2 < 4; ++k2) {
            uint32_t a[4];
            ldmx4(a, aX_base[p] + k2 * 32);
            #pragma unroll
            for (int jp = 0; jp < 8; ++jp) {
                uint32_t b[4];
                ldmx4(b, b0_base + jp * (16 * LDW0B) + k2 * 32);
                mma_f16a(acc[2 * jp],     a, b);
                mma_f16a(acc[2 * jp + 1], a, b + 2);
            }
        }

        uint32_t ap[8][4];
        #pragma unroll
        for (int kk = 0; kk < 8; ++kk) {
            ap[kk][0] = hmax2z(acc[2 * kk][0]);
            ap[kk][1] = hmax2z(acc[2 * kk][1]);
            ap[kk][2] = hmax2z(acc[2 * kk + 1][0]);
            ap[kk][3] = hmax2z(acc[2 * kk + 1][1]);
        }

        const int ntile = tn_s[p];

        float4 px[4];
        int    psid = -1;
        {
            int r = tid >> 2, q = (tid & 3) * 16;
            long g = (long)ntile * TILE + r;
            bool ok = (ntile < ntiles) && (g < N);
            #pragma unroll
            for (int i = 0; i < 4; ++i) {
                px[i] = make_float4(0.f, 0.f, 0.f, 0.f);
                if (ok) px[i] = *reinterpret_cast<const float4*>(
                            &x[g * F_IN + q + i * 4]);
            }
            long gi = (long)ntile * TILE + tid;
            if (tid < TILE && ntile < ntiles && gi < N) psid = seg_ids[gi];
        }

        uint32_t acc1[4][2];
        #pragma unroll
        for (int jn = 0; jn < 4; ++jn) {
            float2 bv = *reinterpret_cast<const float2*>(
                &B1s[br * 32 + jn * 8 + 2 * lt]);
            uint32_t bp = h2u(__floats2half2_rn(bv.x, bv.y));
            acc1[jn][0] = bp; acc1[jn][1] = bp;
        }
        #pragma unroll
        for (int kk = 0; kk < 8; ++kk) {
            #pragma unroll
            for (int jp = 0; jp < 2; ++jp) {
                uint32_t b[4];
                ldmx4(b, b1_base + jp * (16 * LDW1B) + kk * 32);
                mma_f16a(acc1[2 * jp],     ap[kk], b);
                mma_f16a(acc1[2 * jp + 1], ap[kk], b + 2);
            }
        }

        #pragma unroll
        for (int jn = 0; jn < 4; ++jn) {
            int col = br * 32 + jn * 8 + 2 * lt;
            int row = r0 + lg;
            uint32_t lo = hmax2z(acc1[jn][0]);
            uint32_t hi = hmax2z(acc1[jn][1]);
            *reinterpret_cast<uint32_t*>(smc + (gs_base[p] - smb) + row * LDGB + col * 2) = lo;
            *reinterpret_cast<uint32_t*>(smc + (gs_base[p] - smb) + (row + 8) * LDGB + col * 2) = hi;
        }

        {
            int r = tid >> 2, q = (tid & 3) * 16;
            uint32_t h0 = h2u(__floats2half2_rn(px[0].x, px[0].y));
            uint32_t h1 = h2u(__floats2half2_rn(px[0].z, px[0].w));
            uint32_t h2 = h2u(__floats2half2_rn(px[1].x, px[1].y));
            uint32_t h3 = h2u(__floats2half2_rn(px[1].z, px[1].w));
            uint32_t h4 = h2u(__floats2half2_rn(px[2].x, px[2].y));
            uint32_t h5 = h2u(__floats2half2_rn(px[2].z, px[2].w));
            uint32_t h6 = h2u(__floats2half2_rn(px[3].x, px[3].y));
            uint32_t h7 = h2u(__floats2half2_rn(px[3].z, px[3].w));
            uint32_t base = aX_base[p ^ 1] - aX_off + r * LDXB + q * 2;
            asm volatile("st.shared.v4.b32 [%0], {%1,%2,%3,%4};" ::
                "r"(base), "r"(h0), "r"(h1), "r"(h2), "r"(h3));
            asm volatile("st.shared.v4.b32 [%0], {%1,%2,%3,%4};" ::
                "r"(base + 16), "r"(h4), "r"(h5), "r"(h6), "r"(h7));
            if (tid < TILE) sid_s[(p ^ 1) * TILE + tid] = psid;
        }
        __syncthreads();

        if (tid < 128) {
            const int cp    = tid & 31;
            const int chunk = tid >> 5;
            const int rbeg = chunk * 16;
            const int rend = min(rbeg + 16, valid);
            const int* sid = &sid_s[p * TILE];
            const char* gsb = smc + (gs_base[p] - smb);
            if (rbeg < rend) {
                int prev = sid[rbeg];
                float rx = 0.f, ry = 0.f;
                for (int r = rbeg; r < rend; ++r) {
                    int sd = sid[r];
                    if (sd != prev) {
                        atomicAdd(&g_segbuf[prev * 64 + 2 * cp], rx);
                        atomicAdd(&g_segbuf[prev * 64 + 2 * cp + 1], ry);
                        rx = 0.f; ry = 0.f; prev = sd;
                    }
                    __half2 h = *reinterpret_cast<const __half2*>(
                        gsb + r * LDGB + cp * 4);
                    float2 f = __half22float2(h);
                    rx += f.x; ry += f.y;
                }
                atomicAdd(&g_segbuf[prev * 64 + 2 * cp], rx);
                atomicAdd(&g_segbuf[prev * 64 + 2 * cp + 1], ry);
            }
        }
        cur = ntile;
        p ^= 1;
    }
}

// ---------------------------------------------------------------- phase B
// One segment pair per warp; shared weight LDS; restores zero invariant.
__global__ __launch_bounds__(256)
void phaseB_kernel(const float* __restrict__ fwd0_w, const float* __restrict__ fwd0_b,
                   const float* __restrict__ fwd1_w, const float* __restrict__ fwd1_b,
                   const float* __restrict__ com0_w, const float* __restrict__ com0_b,
                   const float* __restrict__ com1_w, const float* __restrict__ com1_b,
                   const float* __restrict__ bwd0_w, const float* __restrict__ bwd0_b,
                   const float* __restrict__ bwd1_w, const float* __restrict__ bwd1_b,
                   const float* __restrict__ cost0_w, const float* __restrict__ cost0_b,
                   const float* __restrict__ cost1_w, const float* __restrict__ cost1_b,
                   const float* __restrict__ pol_w,   const float* __restrict__ pol_b,
                   float* __restrict__ out, int S)
{
    __shared__ float s_f0[32 * 64], s_c0[32 * 64], s_b0[32 * 64];
    __shared__ float s_f0b[64], s_c0b[64], s_b0b[64];
    __shared__ float s_f1[64], s_c1[64], s_b1[64];
    __shared__ float s_k0[3 * 64], s_k0b[64];
    __shared__ float s_k1[64 * 32], s_k1b[32];
    __shared__ float s_pol[64];
    __shared__ float s_scal[4];

    const int t = threadIdx.x;
    if (blockIdx.x == 0 && t == 0) g_tilectr = GRID_A;   // reset for next run
    for (int i = t; i < 32 * 64; i += 256) {
        s_f0[i] = fwd0_w[i]; s_c0[i] = com0_w[i]; s_b0[i] = bwd0_w[i];
    }
    for (int i = t; i < 64 * 32; i += 256) s_k1[i] = cost1_w[i];
    if (t < 64) {
        s_f0b[t] = fwd0_b[t]; s_c0b[t] = com0_b[t]; s_b0b[t] = bwd0_b[t];
        s_f1[t] = fwd1_w[t];  s_c1[t] = com1_w[t];  s_b1[t] = bwd1_w[t];
        s_k0b[t] = cost0_b[t]; s_pol[t] = pol_w[t];
    }
    if (t < 3 * 64) s_k0[t] = cost0_w[t];
    if (t < 32) s_k1b[t] = cost1_b[t];
    if (t == 0) {
        s_scal[0] = fwd1_b[0]; s_scal[1] = com1_b[0];
        s_scal[2] = bwd1_b[0]; s_scal[3] = pol_b[0];
    }
    __syncthreads();

    const int l = t & 31;
    const int warp = (blockIdx.x * blockDim.x + t) >> 5;
    const int nwarps = (gridDim.x * blockDim.x) >> 5;

    for (int s0 = warp * 2; s0 < S; s0 += nwarps * 2) {
        const bool ok1 = (s0 + 1 < S);
        const int s1 = ok1 ? s0 + 1 : s0;

        const float stA = g_segbuf[s0 * 64 + l];
        const float srA = g_segbuf[s0 * 64 + 32 + l];
        const float stB = g_segbuf[s1 * 64 + l];
        const float srB = g_segbuf[s1 * 64 + 32 + l];
        // restore zero invariant (exclusive ownership)
        g_segbuf[s0 * 64 + l] = 0.f;
        g_segbuf[s0 * 64 + 32 + l] = 0.f;
        g_segbuf[s1 * 64 + l] = 0.f;
        g_segbuf[s1 * 64 + 32 + l] = 0.f;

        float fA0 = s_f0b[l], fA1 = s_f0b[l + 32];
        float cA0 = s_c0b[l], cA1 = s_c0b[l + 32];
        float bA0 = s_b0b[l], bA1 = s_b0b[l + 32];
        float fB0 = fA0, fB1 = fA1, cB0 = cA0, cB1 = cA1, bB0 = bA0, bB1 = bA1;
        #pragma unroll
        for (int k = 0; k < 32; ++k) {
            float skA = __shfl_sync(0xffffffffu, stA, k);
            float skB = __shfl_sync(0xffffffffu, stB, k);
            float wf0 = s_f0[k * 64 + l],      wf1 = s_f0[k * 64 + l + 32];
            float wc0 = s_c0[k * 64 + l],      wc1 = s_c0[k * 64 + l + 32];
            float wb0 = s_b0[k * 64 + l],      wb1 = s_b0[k * 64 + l + 32];
            fA0 = fmaf(skA, wf0, fA0); fA1 = fmaf(skA, wf1, fA1);
            cA0 = fmaf(skA, wc0, cA0); cA1 = fmaf(skA, wc1, cA1);
            bA0 = fmaf(skA, wb0, bA0); bA1 = fmaf(skA, wb1, bA1);
            fB0 = fmaf(skB, wf0, fB0); fB1 = fmaf(skB, wf1, fB1);
            cB0 = fmaf(skB, wc0, cB0); cB1 = fmaf(skB, wc1, cB1);
            bB0 = fmaf(skB, wb0, bB0); bB1 = fmaf(skB, wb1, bB1);
        }
        float vfA = fmaxf(fA0, 0.f) * s_f1[l] + fmaxf(fA1, 0.f) * s_f1[l + 32];
        float vcA = fmaxf(cA0, 0.f) * s_c1[l] + fmaxf(cA1, 0.f) * s_c1[l + 32];
        float vbA = fmaxf(bA0, 0.f) * s_b1[l] + fmaxf(bA1, 0.f) * s_b1[l + 32];
        float vfB = fmaxf(fB0, 0.f) * s_f1[l] + fmaxf(fB1, 0.f) * s_f1[l + 32];
        float vcB = fmaxf(cB0, 0.f) * s_c1[l] + fmaxf(cB1, 0.f) * s_c1[l + 32];
        float vbB = fmaxf(bB0, 0.f) * s_b1[l] + fmaxf(bB1, 0.f) * s_b1[l + 32];
        #pragma unroll
        for (int o = 16; o > 0; o >>= 1) {
            vfA += __shfl_xor_sync(0xffffffffu, vfA, o);
            vcA += __shfl_xor_sync(0xffffffffu, vcA, o);
            vbA += __shfl_xor_sync(0xffffffffu, vbA, o);
            vfB += __shfl_xor_sync(0xffffffffu, vfB, o);
            vcB += __shfl_xor_sync(0xffffffffu, vcB, o);
            vbB += __shfl_xor_sync(0xffffffffu, vbB, o);
        }
        const float fwdA = vfA + s_scal[0], comA = vcA + s_scal[1], bwdA = vbA + s_scal[2];
        const float fwdB = vfB + s_scal[0], comB = vcB + s_scal[1], bwdB = vbB + s_scal[2];

        float c1aA = fmaf(fwdA, s_k0[l], fmaf(comA, s_k0[64 + l],
                     fmaf(bwdA, s_k0[128 + l], s_k0b[l])));
        float c1bA = fmaf(fwdA, s_k0[l + 32], fmaf(comA, s_k0[64 + l + 32],
                     fmaf(bwdA, s_k0[128 + l + 32], s_k0b[l + 32])));
        float c1aB = fmaf(fwdB, s_k0[l], fmaf(comB, s_k0[64 + l],
                     fmaf(bwdB, s_k0[128 + l], s_k0b[l])));
        float c1bB = fmaf(fwdB, s_k0[l + 32], fmaf(comB, s_k0[64 + l + 32],
                     fmaf(bwdB, s_k0[128 + l + 32], s_k0b[l + 32])));
        c1aA = fmaxf(c1aA, 0.f); c1bA = fmaxf(c1bA, 0.f);
        c1aB = fmaxf(c1aB, 0.f); c1bB = fmaxf(c1bB, 0.f);

        float c2A = s_k1b[l], c2B = s_k1b[l];
        #pragma unroll
        for (int jj = 0; jj < 32; ++jj) {
            float w0 = s_k1[jj * 32 + l];
            float w1 = s_k1[(jj + 32) * 32 + l];
            float aA = __shfl_sync(0xffffffffu, c1aA, jj);
            float bA = __shfl_sync(0xffffffffu, c1bA, jj);
            float aB = __shfl_sync(0xffffffffu, c1aB, jj);
            float bB = __shfl_sync(0xffffffffu, c1bB, jj);
            c2A = fmaf(aA, w0, c2A); c2A = fmaf(bA, w1, c2A);
            c2B = fmaf(aB, w0, c2B); c2B = fmaf(bB, w1, c2B);
        }
        c2A = fmaxf(c2A, 0.f);
        c2B = fmaxf(c2B, 0.f);

        float vA = fmaf(srA, s_pol[l], c2A * s_pol[l + 32]);
        float vB = fmaf(srB, s_pol[l], c2B * s_pol[l + 32]);
        #pragma unroll
        for (int o = 16; o > 0; o >>= 1) {
            vA += __shfl_xor_sync(0xffffffffu, vA, o);
            vB += __shfl_xor_sync(0xffffffffu, vB, o);
        }
        if (l == 0) {
            out[s0] = vA + s_scal[3];
            if (ok1) out[s1] = vB + s_scal[3];
        }
    }
}

// ----------------------------------------------------------------- launch
extern "C" void kernel_launch(void* const* d_in, const int* in_sizes, int n_in,
                              void* d_out, int out_size)
{
    const float* x      = (const float*)d_in[0];
    const int*   sid    = (const int*)  d_in[1];
    const float* tfc0_w = (const float*)d_in[4];
    const float* tfc0_b = (const float*)d_in[5];
    const float* tfc1_w = (const float*)d_in[6];
    const float* tfc1_b = (const float*)d_in[7];
    const float* fwd0_w = (const float*)d_in[8];
    const float* fwd0_b = (const float*)d_in[9];
    const float* fwd1_w = (const float*)d_in[10];
    const float* fwd1_b = (const float*)d_in[11];
    const float* com0_w = (const float*)d_in[12];
    const float* com0_b = (const float*)d_in[13];
    const float* com1_w = (const float*)d_in[14];
    const float* com1_b = (const float*)d_in[15];
    const float* bwd0_w = (const float*)d_in[16];
    const float* bwd0_b = (const float*)d_in[17];
    const float* bwd1_w = (const float*)d_in[18];
    const float* bwd1_b = (const float*)d_in[19];
    const float* rl0_w  = (const float*)d_in[20];
    const float* rl0_b  = (const float*)d_in[21];
    const float* rl1_w  = (const float*)d_in[22];
    const float* rl1_b  = (const float*)d_in[23];
    const float* cost0_w = (const float*)d_in[24];
    const float* cost0_b = (const float*)d_in[25];
    const float* cost1_w = (const float*)d_in[26];
    const float* cost1_b = (const float*)d_in[27];
    const float* pol_w   = (const float*)d_in[28];
    const float* pol_b   = (const float*)d_in[29];

    const int N = in_sizes[0] / F_IN;
    const int S = out_size;

    static int configured = 0;
    if (!configured) {
        cudaFuncSetAttribute(phaseA_mma,
                             cudaFuncAttributeMaxDynamicSharedMemorySize,
                             SMEM_BYTES);
        configured = 1;
    }

    phaseA_mma<<<GRID_A, BLK, SMEM_BYTES>>>(
        x, sid, tfc0_w, tfc0_b, tfc1_w, tfc1_b,
        rl0_w, rl0_b, rl1_w, rl1_b, N);

    phaseB_kernel<<<GRID_B, 256>>>(
        fwd0_w, fwd0_b, fwd1_w, fwd1_b,
        com0_w, com0_b, com1_w, com1_b,
        bwd0_w, bwd0_b, bwd1_w, bwd1_b,
        cost0_w, cost0_b, cost1_w, cost1_b,
        pol_w, pol_b,
        (float*)d_out, S);
}

// round 17
// speedup vs baseline: 1.0219x; 1.0219x over previous
#include <cuda_runtime.h>
#include <cuda_fp16.h>
#include <cstdint>

// ===========================================================================
// Model_55611236549533 — sm_103a.
// phaseA: fp16-acc mma, register-fused L0->L1, dynamic tiles (unchanged).
// phaseB: 512 CTAs, segment pairs per warp, float2 weight layouts (half the
//         LDS instruction count), 4-way split c2 accumulators,
//         restores zero-segbuf invariant + resets tile counter.
// ===========================================================================

#define F_IN   64
#define S_SEG  16384
#define TILE   64
#define BLK    256
#define GRID_A 296
#define GRID_B 512

// strides (bytes)
#define LDW0B 144
#define LDW1B 272
#define LDXB  144
#define LDGB  144

// smem byte offsets (16B aligned)
#define O_W0   0                 // 256*144 = 36864
#define O_W1   36864             // 64*272  = 17408
#define O_X0   54272             // 64*144  =  9216
#define O_X1   63488             //            9216
#define O_G0   72704             //            9216
#define O_G1   81920             //            9216
#define O_B0   91136             // 256 f32 =  1024
#define O_B1   92160             // 64 f32  =   256
#define O_SID  92416             // 128 int =   512
#define O_TN   92928             // 2 int
#define SMEM_BYTES 92944

__device__ float g_segbuf[S_SEG * 64];        // zero at entry (invariant)
__device__ unsigned int g_tilectr = GRID_A;   // reset by phaseB each run

// ---------------------------------------------------------------- PTX utils
__device__ __forceinline__ uint32_t smem_u32(const void* p) {
    uint32_t a;
    asm("{ .reg .u64 t; cvta.to.shared.u64 t, %1; cvt.u32.u64 %0, t; }"
        : "=r"(a) : "l"(p));
    return a;
}
__device__ __forceinline__ uint32_t h2u(__half2 h) {
    return *reinterpret_cast<uint32_t*>(&h);
}
__device__ __forceinline__ uint32_t hmax2z(uint32_t u) {
    __half2 h = *reinterpret_cast<__half2*>(&u);
    __half2 r = __hmax2(h, __float2half2_rn(0.f));
    return *reinterpret_cast<uint32_t*>(&r);
}
__device__ __forceinline__ void ldmx4(uint32_t* r, uint32_t addr) {
    asm volatile("ldmatrix.sync.aligned.m8n8.x4.shared.b16 {%0,%1,%2,%3}, [%4];"
                 : "=r"(r[0]), "=r"(r[1]), "=r"(r[2]), "=r"(r[3]) : "r"(addr));
}
__device__ __forceinline__ void mma_f16a(uint32_t* d, const uint32_t* a,
                                         const uint32_t* b) {
    asm volatile(
        "mma.sync.aligned.m16n8k16.row.col.f16.f16.f16.f16 "
        "{%0,%1}, {%2,%3,%4,%5}, {%6,%7}, {%0,%1};"
        : "+r"(d[0]), "+r"(d[1])
        : "r"(a[0]), "r"(a[1]), "r"(a[2]), "r"(a[3]), "r"(b[0]), "r"(b[1]));
}

// -------------------------------------------------------------- phase A
__global__ __launch_bounds__(BLK, 2)
void phaseA_mma(const float* __restrict__ x,
                const int*   __restrict__ seg_ids,
                const float* __restrict__ tfc0_w, const float* __restrict__ tfc0_b,
                const float* __restrict__ tfc1_w, const float* __restrict__ tfc1_b,
                const float* __restrict__ rl0_w,  const float* __restrict__ rl0_b,
                const float* __restrict__ rl1_w,  const float* __restrict__ rl1_b,
                int N)
{
    extern __shared__ char smc[];
    __half* W0s = (__half*)(smc + O_W0);
    __half* W1s = (__half*)(smc + O_W1);
    float*  B0s = (float*)(smc + O_B0);
    float*  B1s = (float*)(smc + O_B1);
    int*    sid_s = (int*)(smc + O_SID);
    int*    tn_s  = (int*)(smc + O_TN);
    const uint32_t smb = smem_u32(smc);

    const int tid  = threadIdx.x;
    const int wid  = tid >> 5;
    const int lane = tid & 31;
    const int lg   = lane >> 2;
    const int lt   = lane & 3;

    for (int i = tid; i < 64 * 128; i += BLK) {
        int k = i >> 7, n = i & 127;
        W0s[n * 72 + k]         = __float2half_rn(tfc0_w[i]);
        W0s[(n + 128) * 72 + k] = __float2half_rn(rl0_w[i]);
    }
    for (int i = tid; i < 128 * 32; i += BLK) {
        int k = i >> 5, n = i & 31;
        W1s[n * 136 + k]        = __float2half_rn(tfc1_w[i]);
        W1s[(32 + n) * 136 + k] = __float2half_rn(rl1_w[i]);
    }
    if (tid < 128) { B0s[tid] = tfc0_b[tid]; B0s[128 + tid] = rl0_b[tid]; }
    if (tid < 32)  { B1s[tid] = tfc1_b[tid]; B1s[32 + tid] = rl1_b[tid]; }

    const int ntiles = (N + TILE - 1) / TILE;

    int cur = blockIdx.x;
    {
        int r = tid >> 2, q = (tid & 3) * 16;
        long g = (long)cur * TILE + r;
        bool ok = (cur < ntiles) && (g < N);
        float4 v0 = make_float4(0.f,0.f,0.f,0.f), v1 = v0, v2 = v0, v3 = v0;
        if (ok) {
            const float4* xp = reinterpret_cast<const float4*>(&x[g * F_IN + q]);
            v0 = xp[0]; v1 = xp[1]; v2 = xp[2]; v3 = xp[3];
        }
        uint32_t h0 = h2u(__floats2half2_rn(v0.x, v0.y));
        uint32_t h1 = h2u(__floats2half2_rn(v0.z, v0.w));
        uint32_t h2 = h2u(__floats2half2_rn(v1.x, v1.y));
        uint32_t h3 = h2u(__floats2half2_rn(v1.z, v1.w));
        uint32_t h4 = h2u(__floats2half2_rn(v2.x, v2.y));
        uint32_t h5 = h2u(__floats2half2_rn(v2.z, v2.w));
        uint32_t h6 = h2u(__floats2half2_rn(v3.x, v3.y));
        uint32_t h7 = h2u(__floats2half2_rn(v3.z, v3.w));
        uint32_t base = smb + O_X0 + r * LDXB + q * 2;
        asm volatile("st.shared.v4.b32 [%0], {%1,%2,%3,%4};" ::
            "r"(base), "r"(h0), "r"(h1), "r"(h2), "r"(h3));
        asm volatile("st.shared.v4.b32 [%0], {%1,%2,%3,%4};" ::
            "r"(base + 16), "r"(h4), "r"(h5), "r"(h6), "r"(h7));
        if (tid < TILE) {
            long gi = (long)cur * TILE + tid;
            sid_s[tid] = (cur < ntiles && gi < N) ? seg_ids[gi] : -1;
        }
        if (tid == 0)
            tn_s[0] = (int)atomicAdd(&g_tilectr, 1u);
    }
    __syncthreads();

    const int r0 = (wid & 3) * 16;
    const int br = wid >> 2;

    const uint32_t aX_off = (uint32_t)((r0 + (lane & 15)) * LDXB +
                                       ((lane >> 4) << 3) * 2);
    const uint32_t aX_base[2] = { smb + O_X0 + aX_off, smb + O_X1 + aX_off };
    const uint32_t b0_base = smb + O_W0 +
        (br * 128 + ((lane >> 4) << 3) + (lane & 7)) * LDW0B +
        ((lane >> 3) & 1) * 16;
    const uint32_t b1_base = smb + O_W1 +
        (br * 32 + ((lane >> 4) << 3) + (lane & 7)) * LDW1B +
        ((lane >> 3) & 1) * 16;
    const uint32_t gs_base[2] = { smb + O_G0, smb + O_G1 };

    int p = 0;
    while (cur < ntiles) {
        const int valid = min(TILE, N - cur * TILE);

        if (tid == 0)
            tn_s[p ^ 1] = (int)atomicAdd(&g_tilectr, 1u);

        uint32_t acc[16][2];
        #pragma unroll
        for (int j = 0; j < 16; ++j) {
            float2 bv = *reinterpret_cast<const float2*>(
                &B0s[br * 128 + j * 8 + 2 * lt]);
            uint32_t bp = h2u(__floats2half2_rn(bv.x, bv.y));
            acc[j][0] = bp; acc[j][1] = bp;
        }
        #pragma unroll
        for (int k2 = 0; k2 < 4; ++k2) {
            uint32_t a[4];
            ldmx4(a, aX_base[p] + k2 * 32);
            #pragma unroll
            for (int jp = 0; jp < 8; ++jp) {
                uint32_t b[4];
                ldmx4(b, b0_base + jp * (16 * LDW0B) + k2 * 32);
                mma_f16a(acc[2 * jp],     a, b);
                mma_f16a(acc[2 * jp + 1], a, b + 2);
            }
        }

        uint32_t ap[8][4];
        #pragma unroll
        for (int kk = 0; kk < 8; ++kk) {
            ap[kk][0] = hmax2z(acc[2 * kk][0]);
            ap[kk][1] = hmax2z(acc[2 * kk][1]);
            ap[kk][2] = hmax2z(acc[2 * kk + 1][0]);
            ap[kk][3] = hmax2z(acc[2 * kk + 1][1]);
        }

        const int ntile = tn_s[p];

        float4 px[4];
        int    psid = -1;
        {
            int r = tid >> 2, q = (tid & 3) * 16;
            long g = (long)ntile * TILE + r;
            bool ok = (ntile < ntiles) && (g < N);
            #pragma unroll
            for (int i = 0; i < 4; ++i) {
                px[i] = make_float4(0.f, 0.f, 0.f, 0.f);
                if (ok) px[i] = *reinterpret_cast<const float4*>(
                            &x[g * F_IN + q + i * 4]);
            }
            long gi = (long)ntile * TILE + tid;
            if (tid < TILE && ntile < ntiles && gi < N) psid = seg_ids[gi];
        }

        uint32_t acc1[4][2];
        #pragma unroll
        for (int jn = 0; jn < 4; ++jn) {
            float2 bv = *reinterpret_cast<const float2*>(
                &B1s[br * 32 + jn * 8 + 2 * lt]);
            uint32_t bp = h2u(__floats2half2_rn(bv.x, bv.y));
            acc1[jn][0] = bp; acc1[jn][1] = bp;
        }
        #pragma unroll
        for (int kk = 0; kk < 8; ++kk) {
            #pragma unroll
            for (int jp = 0; jp < 2; ++jp) {
                uint32_t b[4];
                ldmx4(b, b1_base + jp * (16 * LDW1B) + kk * 32);
                mma_f16a(acc1[2 * jp],     ap[kk], b);
                mma_f16a(acc1[2 * jp + 1], ap[kk], b + 2);
            }
        }

        #pragma unroll
        for (int jn = 0; jn < 4; ++jn) {
            int col = br * 32 + jn * 8 + 2 * lt;
            int row = r0 + lg;
            uint32_t lo = hmax2z(acc1[jn][0]);
            uint32_t hi = hmax2z(acc1[jn][1]);
            *reinterpret_cast<uint32_t*>(smc + (gs_base[p] - smb) + row * LDGB + col * 2) = lo;
            *reinterpret_cast<uint32_t*>(smc + (gs_base[p] - smb) + (row + 8) * LDGB + col * 2) = hi;
        }

        {
            int r = tid >> 2, q = (tid & 3) * 16;
            uint32_t h0 = h2u(__floats2half2_rn(px[0].x, px[0].y));
            uint32_t h1 = h2u(__floats2half2_rn(px[0].z, px[0].w));
            uint32_t h2 = h2u(__floats2half2_rn(px[1].x, px[1].y));
            uint32_t h3 = h2u(__floats2half2_rn(px[1].z, px[1].w));
            uint32_t h4 = h2u(__floats2half2_rn(px[2].x, px[2].y));
            uint32_t h5 = h2u(__floats2half2_rn(px[2].z, px[2].w));
            uint32_t h6 = h2u(__floats2half2_rn(px[3].x, px[3].y));
            uint32_t h7 = h2u(__floats2half2_rn(px[3].z, px[3].w));
            uint32_t base = aX_base[p ^ 1] - aX_off + r * LDXB + q * 2;
            asm volatile("st.shared.v4.b32 [%0], {%1,%2,%3,%4};" ::
                "r"(base), "r"(h0), "r"(h1), "r"(h2), "r"(h3));
            asm volatile("st.shared.v4.b32 [%0], {%1,%2,%3,%4};" ::
                "r"(base + 16), "r"(h4), "r"(h5), "r"(h6), "r"(h7));
            if (tid < TILE) sid_s[(p ^ 1) * TILE + tid] = psid;
        }
        __syncthreads();

        if (tid < 128) {
            const int cp    = tid & 31;
            const int chunk = tid >> 5;
            const int rbeg = chunk * 16;
            const int rend = min(rbeg + 16, valid);
            const int* sid = &sid_s[p * TILE];
            const char* gsb = smc + (gs_base[p] - smb);
            if (rbeg < rend) {
                int prev = sid[rbeg];
                float rx = 0.f, ry = 0.f;
                for (int r = rbeg; r < rend; ++r) {
                    int sd = sid[r];
                    if (sd != prev) {
                        atomicAdd(&g_segbuf[prev * 64 + 2 * cp], rx);
                        atomicAdd(&g_segbuf[prev * 64 + 2 * cp + 1], ry);
                        rx = 0.f; ry = 0.f; prev = sd;
                    }
                    __half2 h = *reinterpret_cast<const __half2*>(
                        gsb + r * LDGB + cp * 4);
                    float2 f = __half22float2(h);
                    rx += f.x; ry += f.y;
                }
                atomicAdd(&g_segbuf[prev * 64 + 2 * cp], rx);
                atomicAdd(&g_segbuf[prev * 64 + 2 * cp + 1], ry);
            }
        }
        cur = ntile;
        p ^= 1;
    }
}

// ---------------------------------------------------------------- phase B
__global__ __launch_bounds__(256)
void phaseB_kernel(const float* __restrict__ fwd0_w, const float* __restrict__ fwd0_b,
                   const float* __restrict__ fwd1_w, const float* __restrict__ fwd1_b,
                   const float* __restrict__ com0_w, const float* __restrict__ com0_b,
                   const float* __restrict__ com1_w, const float* __restrict__ com1_b,
                   const float* __restrict__ bwd0_w, const float* __restrict__ bwd0_b,
                   const float* __restrict__ bwd1_w, const float* __restrict__ bwd1_b,
                   const float* __restrict__ cost0_w, const float* __restrict__ cost0_b,
                   const float* __restrict__ cost1_w, const float* __restrict__ cost1_b,
                   const float* __restrict__ pol_w,   const float* __restrict__ pol_b,
                   float* __restrict__ out, int S)
{
    __shared__ float2 s_f0p[32 * 32], s_c0p[32 * 32], s_b0p[32 * 32];
    __shared__ float2 s_k1p[32 * 32];
    __shared__ float s_f0b[64], s_c0b[64], s_b0b[64];
    __shared__ float s_f1[64], s_c1[64], s_b1[64];
    __shared__ float s_k0[3 * 64], s_k0b[64];
    __shared__ float s_k1b[32];
    __shared__ float s_pol[64];
    __shared__ float s_scal[4];

    const int t = threadIdx.x;
    if (blockIdx.x == 0 && t == 0) g_tilectr = GRID_A;   // reset for next run
    for (int i = t; i < 32 * 32; i += 256) {
        int k = i >> 5, li = i & 31;
        s_f0p[i] = make_float2(fwd0_w[k * 64 + li], fwd0_w[k * 64 + li + 32]);
        s_c0p[i] = make_float2(com0_w[k * 64 + li], com0_w[k * 64 + li + 32]);
        s_b0p[i] = make_float2(bwd0_w[k * 64 + li], bwd0_w[k * 64 + li + 32]);
        s_k1p[i] = make_float2(cost1_w[k * 32 + li], cost1_w[(k + 32) * 32 + li]);
    }
    if (t < 64) {
        s_f0b[t] = fwd0_b[t]; s_c0b[t] = com0_b[t]; s_b0b[t] = bwd0_b[t];
        s_f1[t] = fwd1_w[t];  s_c1[t] = com1_w[t];  s_b1[t] = bwd1_w[t];
        s_k0b[t] = cost0_b[t]; s_pol[t] = pol_w[t];
    }
    if (t < 3 * 64) s_k0[t] = cost0_w[t];
    if (t < 32) s_k1b[t] = cost1_b[t];
    if (t == 0) {
        s_scal[0] = fwd1_b[0]; s_scal[1] = com1_b[0];
        s_scal[2] = bwd1_b[0]; s_scal[3] = pol_b[0];
    }
    __syncthreads();

    const int l = t & 31;
    const int warp = (blockIdx.x * blockDim.x + t) >> 5;
    const int nwarps = (gridDim.x * blockDim.x) >> 5;

    for (int s0 = warp * 2; s0 < S; s0 += nwarps * 2) {
        const bool ok1 = (s0 + 1 < S);
        const int s1 = ok1 ? s0 + 1 : s0;

        const float stA = g_segbuf[s0 * 64 + l];
        const float srA = g_segbuf[s0 * 64 + 32 + l];
        const float stB = g_segbuf[s1 * 64 + l];
        const float srB = g_segbuf[s1 * 64 + 32 + l];
        g_segbuf[s0 * 64 + l] = 0.f;
        g_segbuf[s0 * 64 + 32 + l] = 0.f;
        g_segbuf[s1 * 64 + l] = 0.f;
        g_segbuf[s1 * 64 + 32 + l] = 0.f;

        float fA0 = s_f0b[l], fA1 = s_f0b[l + 32];
        float cA0 = s_c0b[l], cA1 = s_c0b[l + 32];
        float bA0 = s_b0b[l], bA1 = s_b0b[l + 32];
        float fB0 = fA0, fB1 = fA1, cB0 = cA0, cB1 = cA1, bB0 = bA0, bB1 = bA1;
        #pragma unroll
        for (int k = 0; k < 32; ++k) {
            float skA = __shfl_sync(0xffffffffu, stA, k);
            float skB = __shfl_sync(0xffffffffu, stB, k);
            float2 wf = s_f0p[k * 32 + l];
            float2 wc = s_c0p[k * 32 + l];
            float2 wb = s_b0p[k * 32 + l];
            fA0 = fmaf(skA, wf.x, fA0); fA1 = fmaf(skA, wf.y, fA1);
            cA0 = fmaf(skA, wc.x, cA0); cA1 = fmaf(skA, wc.y, cA1);
            bA0 = fmaf(skA, wb.x, bA0); bA1 = fmaf(skA, wb.y, bA1);
            fB0 = fmaf(skB, wf.x, fB0); fB1 = fmaf(skB, wf.y, fB1);
            cB0 = fmaf(skB, wc.x, cB0); cB1 = fmaf(skB, wc.y, cB1);
            bB0 = fmaf(skB, wb.x, bB0); bB1 = fmaf(skB, wb.y, bB1);
        }
        float vfA = fmaxf(fA0, 0.f) * s_f1[l] + fmaxf(fA1, 0.f) * s_f1[l + 32];
        float vcA = fmaxf(cA0, 0.f) * s_c1[l] + fmaxf(cA1, 0.f) * s_c1[l + 32];
        float vbA = fmaxf(bA0, 0.f) * s_b1[l] + fmaxf(bA1, 0.f) * s_b1[l + 32];
        float vfB = fmaxf(fB0, 0.f) * s_f1[l] + fmaxf(fB1, 0.f) * s_f1[l + 32];
        float vcB = fmaxf(cB0, 0.f) * s_c1[l] + fmaxf(cB1, 0.f) * s_c1[l + 32];
        float vbB = fmaxf(bB0, 0.f) * s_b1[l] + fmaxf(bB1, 0.f) * s_b1[l + 32];
        #pragma unroll
        for (int o = 16; o > 0; o >>= 1) {
            vfA += __shfl_xor_sync(0xffffffffu, vfA, o);
            vcA += __shfl_xor_sync(0xffffffffu, vcA, o);
            vbA += __shfl_xor_sync(0xffffffffu, vbA, o);
            vfB += __shfl_xor_sync(0xffffffffu, vfB, o);
            vcB += __shfl_xor_sync(0xffffffffu, vcB, o);
            vbB += __shfl_xor_sync(0xffffffffu, vbB, o);
        }
        const float fwdA = vfA + s_scal[0], comA = vcA + s_scal[1], bwdA = vbA + s_scal[2];
        const float fwdB = vfB + s_scal[0], comB = vcB + s_scal[1], bwdB = vbB + s_scal[2];

        float c1aA = fmaf(fwdA, s_k0[l], fmaf(comA, s_k0[64 + l],
                     fmaf(bwdA, s_k0[128 + l], s_k0b[l])));
        float c1bA = fmaf(fwdA, s_k0[l + 32], fmaf(comA, s_k0[64 + l + 32],
                     fmaf(bwdA, s_k0[128 + l + 32], s_k0b[l + 32])));
        float c1aB = fmaf(fwdB, s_k0[l], fmaf(comB, s_k0[64 + l],
                     fmaf(bwdB, s_k0[128 + l], s_k0b[l])));
        float c1bB = fmaf(fwdB, s_k0[l + 32], fmaf(comB, s_k0[64 + l + 32],
                     fmaf(bwdB, s_k0[128 + l + 32], s_k0b[l + 32])));
        c1aA = fmaxf(c1aA, 0.f); c1bA = fmaxf(c1bA, 0.f);
        c1aB = fmaxf(c1aB, 0.f); c1bB = fmaxf(c1bB, 0.f);

        float c2A0 = s_k1b[l], c2A1 = 0.f, c2A2 = 0.f, c2A3 = 0.f;
        float c2B0 = s_k1b[l], c2B1 = 0.f, c2B2 = 0.f, c2B3 = 0.f;
        #pragma unroll
        for (int jj = 0; jj < 32; jj += 2) {
            float2 w0 = s_k1p[jj * 32 + l];
            float2 w1 = s_k1p[(jj + 1) * 32 + l];
            float aA0 = __shfl_sync(0xffffffffu, c1aA, jj);
            float bA0v = __shfl_sync(0xffffffffu, c1bA, jj);
            float aA1 = __shfl_sync(0xffffffffu, c1aA, jj + 1);
            float bA1v = __shfl_sync(0xffffffffu, c1bA, jj + 1);
            float aB0 = __shfl_sync(0xffffffffu, c1aB, jj);
            float bB0v = __shfl_sync(0xffffffffu, c1bB, jj);
            float aB1 = __shfl_sync(0xffffffffu, c1aB, jj + 1);
            float bB1v = __shfl_sync(0xffffffffu, c1bB, jj + 1);
            c2A0 = fmaf(aA0, w0.x, c2A0); c2A1 = fmaf(bA0v, w0.y, c2A1);
            c2A2 = fmaf(aA1, w1.x, c2A2); c2A3 = fmaf(bA1v, w1.y, c2A3);
            c2B0 = fmaf(aB0, w0.x, c2B0); c2B1 = fmaf(bB0v, w0.y, c2B1);
            c2B2 = fmaf(aB1, w1.x, c2B2); c2B3 = fmaf(bB1v, w1.y, c2B3);
        }
        float c2A = fmaxf((c2A0 + c2A1) + (c2A2 + c2A3), 0.f);
        float c2B = fmaxf((c2B0 + c2B1) + (c2B2 + c2B3), 0.f);

        float vA = fmaf(srA, s_pol[l], c2A * s_pol[l + 32]);
        float vB = fmaf(srB, s_pol[l], c2B * s_pol[l + 32]);
        #pragma unroll
        for (int o = 16; o > 0; o >>= 1) {
            vA += __shfl_xor_sync(0xffffffffu, vA, o);
            vB += __shfl_xor_sync(0xffffffffu, vB, o);
        }
        if (l == 0) {
            out[s0] = vA + s_scal[3];
            if (ok1) out[s1] = vB + s_scal[3];
        }
    }
}

// ----------------------------------------------------------------- launch
extern "C" void kernel_launch(void* const* d_in, const int* in_sizes, int n_in,
                              void* d_out, int out_size)
{
    const float* x      = (const float*)d_in[0];
    const int*   sid    = (const int*)  d_in[1];
    const float* tfc0_w = (const float*)d_in[4];
    const float* tfc0_b = (const float*)d_in[5];
    const float* tfc1_w = (const float*)d_in[6];
    const float* tfc1_b = (const float*)d_in[7];
    const float* fwd0_w = (const float*)d_in[8];
    const float* fwd0_b = (const float*)d_in[9];
    const float* fwd1_w = (const float*)d_in[10];
    const float* fwd1_b = (const float*)d_in[11];
    const float* com0_w = (const float*)d_in[12];
    const float* com0_b = (const float*)d_in[13];
    const float* com1_w = (const float*)d_in[14];
    const float* com1_b = (const float*)d_in[15];
    const float* bwd0_w = (const float*)d_in[16];
    const float* bwd0_b = (const float*)d_in[17];
    const float* bwd1_w = (const float*)d_in[18];
    const float* bwd1_b = (const float*)d_in[19];
    const float* rl0_w  = (const float*)d_in[20];
    const float* rl0_b  = (const float*)d_in[21];
    const float* rl1_w  = (const float*)d_in[22];
    const float* rl1_b  = (const float*)d_in[23];
    const float* cost0_w = (const float*)d_in[24];
    const float* cost0_b = (const float*)d_in[25];
    const float* cost1_w = (const float*)d_in[26];
    const float* cost1_b = (const float*)d_in[27];
    const float* pol_w   = (const float*)d_in[28];
    const float* pol_b   = (const float*)d_in[29];

    const int N = in_sizes[0] / F_IN;
    const int S = out_size;

    static int configured = 0;
    if (!configured) {
        cudaFuncSetAttribute(phaseA_mma,
                             cudaFuncAttributeMaxDynamicSharedMemorySize,
                             SMEM_BYTES);
        configured = 1;
    }

    phaseA_mma<<<GRID_A, BLK, SMEM_BYTES>>>(
        x, sid, tfc0_w, tfc0_b, tfc1_w, tfc1_b,
        rl0_w, rl0_b, rl1_w, rl1_b, N);

    phaseB_kernel<<<GRID_B, 256>>>(
        fwd0_w, fwd0_b, fwd1_w, fwd1_b,
        com0_w, com0_b, com1_w, com1_b,
        bwd0_w, bwd0_b, bwd1_w, bwd1_b,
        cost0_w, cost0_b, cost1_w, cost1_b,
        pol_w, pol_b,
        (float*)d_out, S);
}